// round 9
// baseline (speedup 1.0000x reference)
#include <cuda_runtime.h>
#include <cuda_fp16.h>
#include <cstdint>

// HypercomplexLinear via DFT-4 diagonalization + fp16 mma.sync m16n8k16.
//   a0 = X0@W0'^T/4 (K=192), a2 = X2@W2'^T/4 (K=192),
//   P = (Xr@Wr^T - Xs@Ws^T)/2, Q = (Xr@Ws^T + Xs@Wr^T)/2   (K=384)
//   out_0=a0+a2+P, out_1=a0-a2+Q, out_2=a0+a2-P, out_3=a0-a2-Q  (+bias)
// G = [Out0|Out2|P|Q] fp16 intermediate; combine pass to fp32 out.
// GEMM: single-wave persistent CTAs — grid (6,49), each CTA runs 4 tiles
// (2 PQ + 1 a0 + 1 a2 = 18 K-chunks) through ONE continuous cp.async pipeline.

#define M_DIM 6272
#define KX    768

__device__ __half g_Xt[M_DIM * KX];   // [X0|X2|Xr|Xs], canonical k order
// a0 tiles [0,147456): 6 x (3 chunks x 128n x 64k); a2 [147456,294912);
// PQ [294912,...): 12 x (6 chunks x 128n x 64k)  (0..5=P, 6..11=Q)
__device__ __half g_Bp[884736];
__device__ __half g_G[M_DIM * 3072];  // fp16 intermediate

// ---------------------------------------------------------------------------
// Prep 1: X DFT4 -> fp16. One thread per 8 c per row (150k threads).
// ---------------------------------------------------------------------------
__global__ void prep_xt_kernel(const float* __restrict__ x) {
    int idx = blockIdx.x * blockDim.x + threadIdx.x;   // 6272*24
    int b   = idx / 24;
    int c8  = (idx - b * 24) * 8;
    const float* xb = x + (size_t)b * KX;
    float v[4][8];
#pragma unroll
    for (int j = 0; j < 4; j++) {
        float4 u0 = *reinterpret_cast<const float4*>(xb + j * 192 + c8);
        float4 u1 = *reinterpret_cast<const float4*>(xb + j * 192 + c8 + 4);
        v[j][0]=u0.x; v[j][1]=u0.y; v[j][2]=u0.z; v[j][3]=u0.w;
        v[j][4]=u1.x; v[j][5]=u1.y; v[j][6]=u1.z; v[j][7]=u1.w;
    }
#pragma unroll
    for (int cmp = 0; cmp < 4; cmp++) {
        __half h[8];
#pragma unroll
        for (int k = 0; k < 8; k++) {
            float e = v[0][k] + v[2][k], o = v[1][k] + v[3][k];
            float c = (cmp == 0) ? e + o : (cmp == 1) ? e - o
                    : (cmp == 2) ? v[0][k] - v[2][k] : v[1][k] - v[3][k];
            h[k] = __float2half_rn(c);
        }
        *reinterpret_cast<uint4*>(g_Xt + (size_t)b * KX + cmp * 192 + c8) =
            *reinterpret_cast<const uint4*>(h);
    }
}

// ---------------------------------------------------------------------------
// Prep 2: pack weights -> fp16, [n][64k] rows per chunk, canonical k order.
// ---------------------------------------------------------------------------
__global__ void prep_bp_kernel(const float* __restrict__ w) {
    int idx = blockIdx.x * blockDim.x + threadIdx.x;   // 13824
    float val[64];
    __half* dst;
    if (idx < 4608) {                       // a0 / a2
        int cmp  = idx / 2304;
        int rr   = idx - cmp * 2304;
        int tile = rr / 384;
        int rem  = rr - tile * 384;
        int cc   = rem >> 7;                // chunk 0..2
        int n    = rem & 127;
        int o    = tile * 128 + n;
        const float* b0 = w + o * 192 + cc * 64;
        float sg = cmp ? -1.0f : 1.0f;
#pragma unroll 8
        for (int kk = 0; kk < 64; kk++) {
            float w0 = b0[kk], w1 = b0[147456 + kk];
            float w2 = b0[294912 + kk], w3 = b0[442368 + kk];
            val[kk] = 0.25f * (w0 + sg * w1 + w2 + sg * w3);
        }
        dst = g_Bp + cmp * 147456 + tile * 24576 + cc * 8192 + n * 64;
    } else {                                // PQ
        int i2   = idx - 4608;
        int t12  = i2 / 768;                // 0..11
        int rem  = i2 - t12 * 768;
        int cc   = rem >> 7;                // chunk 0..5
        int n    = rem & 127;
        int isQ  = t12 >= 6;
        int o    = (t12 % 6) * 128 + n;
        int ccx  = (cc < 3 ? cc : cc - 3) * 64;
        const float* b0 = w + o * 192 + ccx;
#pragma unroll 8
        for (int kk = 0; kk < 64; kk++) {
            float d02 = b0[kk] - b0[294912 + kk];
            float d13 = b0[147456 + kk] - b0[442368 + kk];
            float pv, qv;
            if (cc < 3) { pv = 0.5f * d02;  qv = 0.5f * d13; }
            else        { pv = -0.5f * d13; qv = 0.5f * d02; }
            val[kk] = isQ ? qv : pv;
        }
        dst = g_Bp + 294912 + t12 * 49152 + cc * 8192 + n * 64;
    }
    __half h[64];
#pragma unroll
    for (int kk = 0; kk < 64; kk++) h[kk] = __float2half_rn(val[kk]);
#pragma unroll
    for (int q = 0; q < 8; q++)
        reinterpret_cast<uint4*>(dst)[q] = reinterpret_cast<const uint4*>(h)[q];
}

// ---------------------------------------------------------------------------
// Persistent fp16 GEMM. Grid (6, 49); CTA j owns tiles {12+j, 18+j, j, 6+j}
// as chunks 0..5, 6..11, 12..14, 15..17 of one continuous pipeline.
// ---------------------------------------------------------------------------
#define STAGES 3
#define STG_B 32768
#define STAGE_TOTAL (STAGES * STG_B)       // 98304
#define DRAIN_B 8704                        // 32 rows x 136 halfs x 2B
#define SMEM_BYTES (STAGE_TOTAL + DRAIN_B)  // 107008

__device__ __forceinline__ void mma_f16(float* c, uint32_t a0, uint32_t a1,
                                        uint32_t a2, uint32_t a3,
                                        uint32_t b0, uint32_t b1) {
    asm volatile(
        "mma.sync.aligned.m16n8k16.row.col.f32.f16.f16.f32 "
        "{%0,%1,%2,%3}, {%4,%5,%6,%7}, {%8,%9}, {%0,%1,%2,%3};"
        : "+f"(c[0]), "+f"(c[1]), "+f"(c[2]), "+f"(c[3])
        : "r"(a0), "r"(a1), "r"(a2), "r"(a3), "r"(b0), "r"(b1));
}
#define LDSM_X4(r0, r1, r2, r3, a) \
    asm volatile("ldmatrix.sync.aligned.m8n8.x4.shared.b16 {%0,%1,%2,%3}, [%4];" \
                 : "=r"(r0), "=r"(r1), "=r"(r2), "=r"(r3) : "r"(a))

__global__ __launch_bounds__(256, 2)
void gemm_f16_kernel() {
    extern __shared__ char smem[];
    const int j   = blockIdx.x;          // 0..5
    const int bm  = blockIdx.y * 128;

    const int tid  = threadIdx.x;
    const int warp = tid >> 5;
    const int lane = tid & 31;
    const int g    = lane >> 2;
    const int tig  = lane & 3;
    const int wm   = (warp & 1) * 64;
    const int wn   = (warp >> 1) * 32;

    float acc[4][4][4];
#pragma unroll
    for (int mi = 0; mi < 4; mi++)
#pragma unroll
        for (int ni = 0; ni < 4; ni++)
#pragma unroll
            for (int r = 0; r < 4; r++) acc[mi][ni][r] = 0.0f;

    // cp.async loader: 2 threads per row, 4 x 16B chunks each
    const int lrow = tid >> 1;
    const int cseg = (tid & 1) * 4;
    const int ssw  = lrow & 7;
    uint32_t sbase;
    asm("{ .reg .u64 t; cvta.to.shared.u64 t, %1; cvt.u32.u64 %0, t; }"
        : "=r"(sbase) : "l"(smem));

    // q -> (A k-offset in halfs, B byte offset) mapping
    auto load_stage = [&](int q, int s) {
        int aofs, bofs;
        if (q < 12) {                       // PQ tiles 12+j (q 0..5), 18+j (6..11)
            int kt = (q < 6) ? q : q - 6;
            int tile = (q < 6) ? j : 6 + j;
            aofs = 384 + kt * 64;
            bofs = 589824 + tile * 98304 + kt * 16384;
        } else if (q < 15) {                // a0 tile j
            int kt = q - 12;
            aofs = kt * 64;
            bofs = j * 49152 + kt * 16384;
        } else {                            // a2 tile j
            int kt = q - 15;
            aofs = 192 + kt * 64;
            bofs = 294912 + j * 49152 + kt * 16384;
        }
        const char* pa = reinterpret_cast<const char*>(
            g_Xt + (size_t)(bm + lrow) * KX + aofs);
        const char* pb = reinterpret_cast<const char*>(g_Bp) + bofs + lrow * 128;
        uint32_t ab = sbase + (uint32_t)(s * STG_B);
        uint32_t bb = ab + 16384u;
#pragma unroll
        for (int f = 0; f < 4; f++) {
            int c = cseg + f;
            uint32_t wd = (uint32_t)(lrow * 128 + ((c ^ ssw) << 4));
            asm volatile("cp.async.cg.shared.global [%0], [%1], 16;"
                         :: "r"(ab + wd), "l"(pa + c * 16));
            asm volatile("cp.async.cg.shared.global [%0], [%1], 16;"
                         :: "r"(bb + wd), "l"(pb + c * 16));
        }
    };

    // ldmatrix per-lane row mapping
    const int rowA = (lane & 7) + ((lane >> 3) & 1) * 8;
    const int chA  = lane >> 4;
    const int rowB = (lane & 7) + ((lane >> 4) & 1) * 8;
    const int chB  = (lane >> 3) & 1;
    int rA[4], rB[2];
#pragma unroll
    for (int mi = 0; mi < 4; mi++) rA[mi] = wm + mi * 16 + rowA;
#pragma unroll
    for (int n2 = 0; n2 < 2; n2++) rB[n2] = wn + n2 * 16 + rowB;

    auto compute = [&](int s) {
        uint32_t As = sbase + (uint32_t)(s * STG_B);
        uint32_t Bs = As + 16384u;
#pragma unroll
        for (int kg = 0; kg < 4; kg++) {
            uint32_t af[4][4], bf[2][4];
#pragma unroll
            for (int mi = 0; mi < 4; mi++) {
                uint32_t ad = As + (uint32_t)(rA[mi] * 128
                            + (((2 * kg + chA) ^ (rA[mi] & 7)) << 4));
                LDSM_X4(af[mi][0], af[mi][1], af[mi][2], af[mi][3], ad);
            }
#pragma unroll
            for (int n2 = 0; n2 < 2; n2++) {
                uint32_t bd = Bs + (uint32_t)(rB[n2] * 128
                            + (((2 * kg + chB) ^ (rB[n2] & 7)) << 4));
                LDSM_X4(bf[n2][0], bf[n2][1], bf[n2][2], bf[n2][3], bd);
            }
#pragma unroll
            for (int ni = 0; ni < 4; ni++) {
                uint32_t b0 = bf[ni >> 1][(ni & 1) * 2];
                uint32_t b1 = bf[ni >> 1][(ni & 1) * 2 + 1];
#pragma unroll
                for (int mi = 0; mi < 4; mi++)
                    mma_f16(acc[mi][ni], af[mi][0], af[mi][1], af[mi][2], af[mi][3],
                            b0, b1);
            }
        }
    };

    // Drain accumulators for finished tile to g_G (column base bn), then zero.
    __half* stg = reinterpret_cast<__half*>(smem + STAGE_TOTAL);
    auto drain = [&](int bn) {
#pragma unroll
        for (int p = 0; p < 4; p++) {       // rows p*32 .. p*32+31
            if ((warp & 1) == (p >> 1)) {
#pragma unroll
                for (int mm = 0; mm < 2; mm++) {
                    int mi = (p & 1) * 2 + mm;
                    int r0 = mm * 16 + g;
#pragma unroll
                    for (int ni = 0; ni < 4; ni++) {
                        int col = wn + ni * 8 + 2 * tig;
                        *reinterpret_cast<__half2*>(stg + r0 * 136 + col) =
                            __floats2half2_rn(acc[mi][ni][0], acc[mi][ni][1]);
                        *reinterpret_cast<__half2*>(stg + (r0 + 8) * 136 + col) =
                            __floats2half2_rn(acc[mi][ni][2], acc[mi][ni][3]);
                    }
                }
            }
            __syncthreads();
#pragma unroll
            for (int i = 0; i < 2; i++) {
                int linear = tid + 256 * i;
                int row = linear >> 4;
                int qq  = linear & 15;
                uint4 v = *reinterpret_cast<const uint4*>(stg + row * 136 + qq * 8);
                *reinterpret_cast<uint4*>(
                    g_G + (size_t)(bm + p * 32 + row) * 3072 + bn + qq * 8) = v;
            }
            __syncthreads();
        }
#pragma unroll
        for (int mi = 0; mi < 4; mi++)
#pragma unroll
            for (int ni = 0; ni < 4; ni++)
#pragma unroll
                for (int r = 0; r < 4; r++) acc[mi][ni][r] = 0.0f;
    };

    // ---- continuous pipeline over 18 chunks ----
    load_stage(0, 0);
    asm volatile("cp.async.commit_group;");
    load_stage(1, 1);
    asm volatile("cp.async.commit_group;");
    asm volatile("cp.async.wait_group 1;");
    __syncthreads();

    for (int q = 0; q < 18; q++) {
        if (q + 2 < 18) load_stage(q + 2, (q + 2) % 3);
        asm volatile("cp.async.commit_group;");
        compute(q % 3);
        asm volatile("cp.async.wait_group 1;");
        __syncthreads();
        if (q == 5)       drain((12 + j) * 128);
        else if (q == 11) drain((18 + j) * 128);
        else if (q == 14) drain(j * 128);
        else if (q == 17) drain((6 + j) * 128);
    }
}

// ---------------------------------------------------------------------------
// Combine: fp16 G -> fp32 out with bias. One thread per (b, 4 o).
// ---------------------------------------------------------------------------
__global__ void combine_kernel(const float* __restrict__ bias,
                               float* __restrict__ out) {
    int idx = blockIdx.x * blockDim.x + threadIdx.x;   // 6272*192
    int b  = idx / 192;
    int o4 = (idx - b * 192) * 4;
    const __half* Gb = g_G + (size_t)b * 3072;
    __half2 a0[2], a2[2], p[2], q[2];
    *reinterpret_cast<uint2*>(a0) = *reinterpret_cast<const uint2*>(Gb + o4);
    *reinterpret_cast<uint2*>(a2) = *reinterpret_cast<const uint2*>(Gb + 768 + o4);
    *reinterpret_cast<uint2*>(p)  = *reinterpret_cast<const uint2*>(Gb + 1536 + o4);
    *reinterpret_cast<uint2*>(q)  = *reinterpret_cast<const uint2*>(Gb + 2304 + o4);

    float r0[4], r1[4], r2[4], r3[4];
#pragma unroll
    for (int i = 0; i < 2; i++) {
        float2 fa0 = __half22float2(a0[i]);
        float2 fa2 = __half22float2(a2[i]);
        float2 fp  = __half22float2(p[i]);
        float2 fq  = __half22float2(q[i]);
        float sx = fa0.x + fa2.x, sy = fa0.y + fa2.y;
        float dx = fa0.x - fa2.x, dy = fa0.y - fa2.y;
        r0[2*i] = sx + fp.x; r0[2*i+1] = sy + fp.y;
        r1[2*i] = dx + fq.x; r1[2*i+1] = dy + fq.y;
        r2[2*i] = sx - fp.x; r2[2*i+1] = sy - fp.y;
        r3[2*i] = dx - fq.x; r3[2*i+1] = dy - fq.y;
    }
    float* ob = out + (size_t)b * 3072 + o4;
    const float4 bv0 = *reinterpret_cast<const float4*>(bias + o4);
    const float4 bv1 = *reinterpret_cast<const float4*>(bias + 768 + o4);
    const float4 bv2 = *reinterpret_cast<const float4*>(bias + 1536 + o4);
    const float4 bv3 = *reinterpret_cast<const float4*>(bias + 2304 + o4);
    *reinterpret_cast<float4*>(ob) =
        make_float4(r0[0]+bv0.x, r0[1]+bv0.y, r0[2]+bv0.z, r0[3]+bv0.w);
    *reinterpret_cast<float4*>(ob + 768) =
        make_float4(r1[0]+bv1.x, r1[1]+bv1.y, r1[2]+bv1.z, r1[3]+bv1.w);
    *reinterpret_cast<float4*>(ob + 1536) =
        make_float4(r2[0]+bv2.x, r2[1]+bv2.y, r2[2]+bv2.z, r2[3]+bv2.w);
    *reinterpret_cast<float4*>(ob + 2304) =
        make_float4(r3[0]+bv3.x, r3[1]+bv3.y, r3[2]+bv3.z, r3[3]+bv3.w);
}

// ---------------------------------------------------------------------------
extern "C" void kernel_launch(void* const* d_in, const int* in_sizes, int n_in,
                              void* d_out, int out_size) {
    const float* x    = (const float*)d_in[0];
    const float* w    = (const float*)d_in[1];
    const float* bias = (const float*)d_in[2];
    float* out = (float*)d_out;

    cudaFuncSetAttribute(gemm_f16_kernel,
                         cudaFuncAttributeMaxDynamicSharedMemorySize, SMEM_BYTES);

    prep_xt_kernel<<<(M_DIM * 24) / 128, 128>>>(x);     // 1176 blocks
    prep_bp_kernel<<<13824 / 128, 128>>>(w);            // 108 blocks

    dim3 grid(6, 49);
    gemm_f16_kernel<<<grid, 256, SMEM_BYTES>>>();

    combine_kernel<<<(M_DIM * 192) / 256, 256>>>(bias, out);  // 4704 blocks
}